// round 1
// baseline (speedup 1.0000x reference)
#include <cuda_runtime.h>
#include <cuda_bf16.h>
#include <math.h>

#define DF 512
#define MAXN 100000
#define MAXE 3200000

// ---------------- device scratch (no dynamic allocation allowed) -------------
__device__ float g_support[(size_t)MAXN * DF];
__device__ float g_trans[(size_t)MAXN * DF];
__device__ float g_gate[(size_t)MAXN * DF];
__device__ int   g_row_cnt[MAXN];
__device__ int   g_row_start[MAXN];
__device__ int   g_row_cur[MAXN];
__device__ int2  g_edges[MAXE];   // (col, val-as-bits) sorted by row

// ---------------- helpers ----------------------------------------------------
__device__ __forceinline__ unsigned f2tf32(float f) {
    unsigned r;
    asm("cvt.rna.tf32.f32 %0, %1;" : "=r"(r) : "f"(f));
    return r;
}

__device__ __forceinline__ void mma_tf32(float c[4], const unsigned a[4], const unsigned b[2]) {
    asm volatile(
        "mma.sync.aligned.m16n8k8.row.col.f32.tf32.tf32.f32 "
        "{%0,%1,%2,%3}, {%4,%5,%6,%7}, {%8,%9}, {%0,%1,%2,%3};"
        : "+f"(c[0]), "+f"(c[1]), "+f"(c[2]), "+f"(c[3])
        : "r"(a[0]), "r"(a[1]), "r"(a[2]), "r"(a[3]), "r"(b[0]), "r"(b[1]));
}

__device__ __forceinline__ float sigmoidf_fast(float v) {
    return 1.0f / (1.0f + __expf(-v));
}

// ---------------- fused triple GEMM (tf32 tensor cores) ----------------------
// Block tile 128(M) x 64(N), K-tile 32. 256 threads = 8 warps (4x2),
// warp tile 32x32 = 2x4 m16n8k8 fragments.
// z = 0: support = x@w1 ; z = 1: trans = x@w2+b2 ; z = 2: gate = sigmoid(x@w3+b3)
__global__ __launch_bounds__(256) void gemm3_kernel(
    const float* __restrict__ x,
    const float* __restrict__ w1, const float* __restrict__ w2, const float* __restrict__ w3,
    const float* __restrict__ b2, const float* __restrict__ b3, int n)
{
    __shared__ unsigned As[128][36];  // [m][k], pad to 36 to spread banks
    __shared__ unsigned Bs[32][68];   // [k][n], pad to 68

    const int z  = blockIdx.z;
    const float* __restrict__ w = (z == 0) ? w1 : ((z == 1) ? w2 : w3);
    const int bm = blockIdx.x * 128;
    const int bn = blockIdx.y * 64;

    const int t    = threadIdx.x;
    const int lane = t & 31;
    const int warp = t >> 5;
    const int wm   = (warp & 3) * 32;
    const int wn   = (warp >> 2) * 32;
    const int gid  = lane >> 2;   // group id  (0..7)
    const int tig  = lane & 3;    // thread in group (0..3)

    float acc[2][4][4];
#pragma unroll
    for (int mi = 0; mi < 2; mi++)
#pragma unroll
        for (int ni = 0; ni < 4; ni++)
#pragma unroll
            for (int r = 0; r < 4; r++) acc[mi][ni][r] = 0.0f;

    const int arow = t >> 3;           // 0..31
    const int acol = (t & 7) << 2;     // 0..28 step 4
    const int brow = t >> 4;           // 0..15
    const int bcol = (t & 15) << 2;    // 0..60 step 4

    for (int kt = 0; kt < DF; kt += 32) {
        // load A tile 128x32 (tf32-converted)
#pragma unroll
        for (int i = 0; i < 4; i++) {
            const int m  = arow + i * 32;
            const int gm = bm + m;
            float4 v = make_float4(0.f, 0.f, 0.f, 0.f);
            if (gm < n) v = *(const float4*)(x + (size_t)gm * DF + kt + acol);
            As[m][acol + 0] = f2tf32(v.x);
            As[m][acol + 1] = f2tf32(v.y);
            As[m][acol + 2] = f2tf32(v.z);
            As[m][acol + 3] = f2tf32(v.w);
        }
        // load B tile 32x64
#pragma unroll
        for (int i = 0; i < 2; i++) {
            const int k = brow + i * 16;
            const float4 v = *(const float4*)(w + (size_t)(kt + k) * DF + bn + bcol);
            Bs[k][bcol + 0] = f2tf32(v.x);
            Bs[k][bcol + 1] = f2tf32(v.y);
            Bs[k][bcol + 2] = f2tf32(v.z);
            Bs[k][bcol + 3] = f2tf32(v.w);
        }
        __syncthreads();

#pragma unroll
        for (int kk = 0; kk < 32; kk += 8) {
            unsigned a[2][4], b[4][2];
#pragma unroll
            for (int mi = 0; mi < 2; mi++) {
                const int r = wm + mi * 16 + gid;
                a[mi][0] = As[r][kk + tig];
                a[mi][1] = As[r + 8][kk + tig];
                a[mi][2] = As[r][kk + 4 + tig];
                a[mi][3] = As[r + 8][kk + 4 + tig];
            }
#pragma unroll
            for (int ni = 0; ni < 4; ni++) {
                const int cn = wn + ni * 8 + gid;
                b[ni][0] = Bs[kk + tig][cn];
                b[ni][1] = Bs[kk + 4 + tig][cn];
            }
#pragma unroll
            for (int mi = 0; mi < 2; mi++)
#pragma unroll
                for (int ni = 0; ni < 4; ni++)
                    mma_tf32(acc[mi][ni], a[mi], b[ni]);
        }
        __syncthreads();
    }

    // epilogue
    float* __restrict__ outp = (z == 0) ? g_support : ((z == 1) ? g_trans : g_gate);
    const float* __restrict__ bias = (z == 1) ? b2 : b3;

#pragma unroll
    for (int mi = 0; mi < 2; mi++) {
#pragma unroll
        for (int ni = 0; ni < 4; ni++) {
            const int col = bn + wn + ni * 8 + tig * 2;
            const int r0  = bm + wm + mi * 16 + gid;
            float v0 = acc[mi][ni][0], v1 = acc[mi][ni][1];
            float v2 = acc[mi][ni][2], v3 = acc[mi][ni][3];
            if (z >= 1) {
                const float bb0 = bias[col], bb1 = bias[col + 1];
                v0 += bb0; v1 += bb1; v2 += bb0; v3 += bb1;
            }
            if (z == 2) {
                v0 = sigmoidf_fast(v0); v1 = sigmoidf_fast(v1);
                v2 = sigmoidf_fast(v2); v3 = sigmoidf_fast(v3);
            }
            if (r0 < n)
                *(float2*)(outp + (size_t)r0 * DF + col) = make_float2(v0, v1);
            if (r0 + 8 < n)
                *(float2*)(outp + (size_t)(r0 + 8) * DF + col) = make_float2(v2, v3);
        }
    }
}

// ---------------- CSR build --------------------------------------------------
__global__ void zero_cnt_kernel(int n) {
    const int i = blockIdx.x * blockDim.x + threadIdx.x;
    if (i < n) g_row_cnt[i] = 0;
}

__global__ void hist_kernel(const int* __restrict__ er, int E) {
    for (int i = blockIdx.x * blockDim.x + threadIdx.x; i < E; i += gridDim.x * blockDim.x)
        atomicAdd(&g_row_cnt[er[i]], 1);
}

__global__ __launch_bounds__(1024) void scan_kernel(int n) {
    const int T = 1024;
    const int t = threadIdx.x;
    const int chunk = (n + T - 1) / T;
    const int begin = t * chunk;
    const int end   = min(begin + chunk, n);

    int local = 0;
    for (int i = begin; i < end; i++) local += g_row_cnt[i];

    __shared__ int s[1024];
    s[t] = local;
    __syncthreads();
#pragma unroll
    for (int off = 1; off < T; off <<= 1) {
        const int v = (t >= off) ? s[t - off] : 0;
        __syncthreads();
        s[t] += v;
        __syncthreads();
    }
    int run = s[t] - local;  // exclusive prefix
    for (int i = begin; i < end; i++) {
        g_row_start[i] = run;
        g_row_cur[i]   = run;
        run += g_row_cnt[i];
    }
}

__global__ void scatter_kernel(const int* __restrict__ er, const int* __restrict__ ec,
                               const float* __restrict__ ev, int E) {
    for (int i = blockIdx.x * blockDim.x + threadIdx.x; i < E; i += gridDim.x * blockDim.x) {
        const int r = er[i];
        const int p = atomicAdd(&g_row_cur[r], 1);
        g_edges[p] = make_int2(ec[i], __float_as_int(ev[i]));
    }
}

// ---------------- aggregation + fused final epilogue -------------------------
// one block (128 threads) per output row; each thread owns 4 columns (float4)
__global__ __launch_bounds__(128) void aggregate_kernel(
    const float* __restrict__ b1, float* __restrict__ out, int n)
{
    const int row = blockIdx.x;
    const int t   = threadIdx.x;
    const int c   = t << 2;

    const int start = g_row_start[row];
    const int deg   = g_row_cnt[row];

    float4 acc = make_float4(0.f, 0.f, 0.f, 0.f);
    __shared__ int2 se[128];

    for (int base = 0; base < deg; base += 128) {
        const int m = min(128, deg - base);
        if (t < m) se[t] = g_edges[start + base + t];
        __syncthreads();

        int i = 0;
        for (; i + 4 <= m; i += 4) {
            const int2 e0 = se[i], e1 = se[i + 1], e2 = se[i + 2], e3 = se[i + 3];
            const float4 s0 = *(const float4*)(g_support + (size_t)e0.x * DF + c);
            const float4 s1 = *(const float4*)(g_support + (size_t)e1.x * DF + c);
            const float4 s2 = *(const float4*)(g_support + (size_t)e2.x * DF + c);
            const float4 s3 = *(const float4*)(g_support + (size_t)e3.x * DF + c);
            const float v0 = __int_as_float(e0.y), v1 = __int_as_float(e1.y);
            const float v2 = __int_as_float(e2.y), v3 = __int_as_float(e3.y);
            acc.x = fmaf(v0, s0.x, acc.x); acc.y = fmaf(v0, s0.y, acc.y);
            acc.z = fmaf(v0, s0.z, acc.z); acc.w = fmaf(v0, s0.w, acc.w);
            acc.x = fmaf(v1, s1.x, acc.x); acc.y = fmaf(v1, s1.y, acc.y);
            acc.z = fmaf(v1, s1.z, acc.z); acc.w = fmaf(v1, s1.w, acc.w);
            acc.x = fmaf(v2, s2.x, acc.x); acc.y = fmaf(v2, s2.y, acc.y);
            acc.z = fmaf(v2, s2.z, acc.z); acc.w = fmaf(v2, s2.w, acc.w);
            acc.x = fmaf(v3, s3.x, acc.x); acc.y = fmaf(v3, s3.y, acc.y);
            acc.z = fmaf(v3, s3.z, acc.z); acc.w = fmaf(v3, s3.w, acc.w);
        }
        for (; i < m; i++) {
            const int2 e = se[i];
            const float val = __int_as_float(e.y);
            const float4 s = *(const float4*)(g_support + (size_t)e.x * DF + c);
            acc.x = fmaf(val, s.x, acc.x); acc.y = fmaf(val, s.y, acc.y);
            acc.z = fmaf(val, s.z, acc.z); acc.w = fmaf(val, s.w, acc.w);
        }
        __syncthreads();
    }

    const float4 bb = *(const float4*)(b1 + c);
    const size_t off = (size_t)row * DF + c;
    const float4 tr = *(const float4*)(g_trans + off);
    const float4 gt = *(const float4*)(g_gate + off);
    float4 o;
    o.x = fmaxf(acc.x + bb.x, 0.f);  o.x = tr.x + gt.x * (o.x - tr.x);
    o.y = fmaxf(acc.y + bb.y, 0.f);  o.y = tr.y + gt.y * (o.y - tr.y);
    o.z = fmaxf(acc.z + bb.z, 0.f);  o.z = tr.z + gt.z * (o.z - tr.z);
    o.w = fmaxf(acc.w + bb.w, 0.f);  o.w = tr.w + gt.w * (o.w - tr.w);
    *(float4*)(out + off) = o;
}

// ---------------- launch ------------------------------------------------------
extern "C" void kernel_launch(void* const* d_in, const int* in_sizes, int n_in,
                              void* d_out, int out_size)
{
    const float* x  = (const float*)d_in[0];
    const float* w1 = (const float*)d_in[1];
    const float* w2 = (const float*)d_in[2];
    const float* w3 = (const float*)d_in[3];
    const float* b1 = (const float*)d_in[4];
    const float* b2 = (const float*)d_in[5];
    const float* b3 = (const float*)d_in[6];
    const int*   er = (const int*)d_in[7];
    const int*   ec = (const int*)d_in[8];
    const float* ev = (const float*)d_in[9];

    const int n = in_sizes[0] / DF;   // 100000
    const int E = in_sizes[7];        // 3200000
    float* out = (float*)d_out;

    dim3 ggrid((n + 127) / 128, DF / 64, 3);
    gemm3_kernel<<<ggrid, 256>>>(x, w1, w2, w3, b2, b3, n);

    zero_cnt_kernel<<<(n + 255) / 256, 256>>>(n);
    hist_kernel<<<2048, 256>>>(er, E);
    scan_kernel<<<1, 1024>>>(n);
    scatter_kernel<<<2048, 256>>>(er, ec, ev, E);

    aggregate_kernel<<<n, 128>>>(b1, out, n);
}

// round 4
// speedup vs baseline: 1.5642x; 1.5642x over previous
#include <cuda_runtime.h>
#include <cuda_bf16.h>
#include <cuda_fp16.h>
#include <stdint.h>
#include <math.h>

#define DF 512
#define MAXN 100000
#define MAXE 3200000

// ---------------- device scratch (no dynamic allocation allowed) -------------
__device__ __half g_support_h[(size_t)MAXN * DF];
__device__ float  g_trans[(size_t)MAXN * DF];
__device__ float  g_gate[(size_t)MAXN * DF];
__device__ int    g_row_cnt[MAXN];
__device__ int    g_row_start[MAXN];
__device__ int    g_row_cur[MAXN];
__device__ int    g_partials[256];
__device__ int2   g_edges[MAXE];   // (col, val-as-bits) grouped by row

// ---------------- helpers ----------------------------------------------------
__device__ __forceinline__ unsigned f2tf32(float f) {
    unsigned r;
    asm("cvt.rna.tf32.f32 %0, %1;" : "=r"(r) : "f"(f));
    return r;
}

__device__ __forceinline__ void mma_tf32(float c[4], const unsigned a[4], const unsigned b[2]) {
    asm volatile(
        "mma.sync.aligned.m16n8k8.row.col.f32.tf32.tf32.f32 "
        "{%0,%1,%2,%3}, {%4,%5,%6,%7}, {%8,%9}, {%0,%1,%2,%3};"
        : "+f"(c[0]), "+f"(c[1]), "+f"(c[2]), "+f"(c[3])
        : "r"(a[0]), "r"(a[1]), "r"(a[2]), "r"(a[3]), "r"(b[0]), "r"(b[1]));
}

__device__ __forceinline__ void cp16(unsigned int dst, const void* src, bool valid) {
    int sz = valid ? 16 : 0;
    asm volatile("cp.async.cg.shared.global [%0], [%1], 16, %2;"
                 :: "r"(dst), "l"(src), "r"(sz));
}
__device__ __forceinline__ void cp_commit() { asm volatile("cp.async.commit_group;"); }
__device__ __forceinline__ void cp_wait1()  { asm volatile("cp.async.wait_group 1;"); }

__device__ __forceinline__ float sigmoidf_fast(float v) {
    return 1.0f / (1.0f + __expf(-v));
}

// ---------------- fused triple GEMM (tf32 tensor cores, cp.async pipeline) ---
// Block tile 128(M) x 128(N), K-tile 16, double-buffered via cp.async.
// 256 threads = 8 warps (4 M x 2 N), warp tile 32x64 = 2x8 m16n8k8 fragments.
// z = 0: support(h) = x@w1 ; z = 1: trans = x@w2+b2 ; z = 2: gate = sigmoid(x@w3+b3)
struct PfIdx {
    int a_row0, a_col0, a_row1, a_col1;
    int b_row0, b_col0, b_row1, b_col1;
};

__device__ __forceinline__ void prefetch_tile(
    float (*As)[128][20], float (*Bs)[16][132], int bf,
    const float* __restrict__ x, const float* __restrict__ w,
    int bm, int bn, int k0, int n, const PfIdx& p)
{
    unsigned int da0 = (unsigned int)__cvta_generic_to_shared(&As[bf][p.a_row0][p.a_col0]);
    unsigned int da1 = (unsigned int)__cvta_generic_to_shared(&As[bf][p.a_row1][p.a_col1]);
    cp16(da0, x + (size_t)(bm + p.a_row0) * DF + k0 + p.a_col0, (bm + p.a_row0) < n);
    cp16(da1, x + (size_t)(bm + p.a_row1) * DF + k0 + p.a_col1, (bm + p.a_row1) < n);
    unsigned int db0 = (unsigned int)__cvta_generic_to_shared(&Bs[bf][p.b_row0][p.b_col0]);
    unsigned int db1 = (unsigned int)__cvta_generic_to_shared(&Bs[bf][p.b_row1][p.b_col1]);
    cp16(db0, w + (size_t)(k0 + p.b_row0) * DF + bn + p.b_col0, true);
    cp16(db1, w + (size_t)(k0 + p.b_row1) * DF + bn + p.b_col1, true);
}

__global__ __launch_bounds__(256) void gemm3_kernel(
    const float* __restrict__ x,
    const float* __restrict__ w1, const float* __restrict__ w2, const float* __restrict__ w3,
    const float* __restrict__ b2, const float* __restrict__ b3, int n)
{
    __shared__ float As[2][128][20];   // [m][k] pad 20
    __shared__ float Bs[2][16][132];   // [k][n] pad 132

    const int z  = blockIdx.z;
    const float* __restrict__ w = (z == 0) ? w1 : ((z == 1) ? w2 : w3);
    const int bm = blockIdx.x * 128;
    const int bn = blockIdx.y * 128;

    const int t    = threadIdx.x;
    const int lane = t & 31;
    const int warp = t >> 5;
    const int wm   = (warp & 3) * 32;
    const int wn   = (warp >> 2) * 64;
    const int gid  = lane >> 2;
    const int tig  = lane & 3;

    float acc[2][8][4];
#pragma unroll
    for (int mi = 0; mi < 2; mi++)
#pragma unroll
        for (int ni = 0; ni < 8; ni++)
#pragma unroll
            for (int r = 0; r < 4; r++) acc[mi][ni][r] = 0.0f;

    PfIdx p;
    p.a_row0 = t >> 2;
    p.a_col0 = (t & 3) * 4;
    p.a_row1 = (t + 256) >> 2;
    p.a_col1 = ((t + 256) & 3) * 4;
    p.b_row0 = t >> 5;
    p.b_col0 = (t & 31) * 4;
    p.b_row1 = (t + 256) >> 5;
    p.b_col1 = ((t + 256) & 31) * 4;

    const int NT = DF / 16;   // 32 k-tiles
    int cb = 0;
    prefetch_tile(As, Bs, 0, x, w, bm, bn, 0, n, p);
    cp_commit();

    for (int kt = 0; kt < NT; kt++) {
        if (kt + 1 < NT)
            prefetch_tile(As, Bs, cb ^ 1, x, w, bm, bn, (kt + 1) * 16, n, p);
        cp_commit();
        cp_wait1();
        __syncthreads();

#pragma unroll
        for (int kk = 0; kk < 16; kk += 8) {
            unsigned a[2][4];
#pragma unroll
            for (int mi = 0; mi < 2; mi++) {
                const int r = wm + mi * 16 + gid;
                a[mi][0] = f2tf32(As[cb][r][kk + tig]);
                a[mi][1] = f2tf32(As[cb][r + 8][kk + tig]);
                a[mi][2] = f2tf32(As[cb][r][kk + 4 + tig]);
                a[mi][3] = f2tf32(As[cb][r + 8][kk + 4 + tig]);
            }
            unsigned b[8][2];
#pragma unroll
            for (int ni = 0; ni < 8; ni++) {
                const int cn = wn + ni * 8 + gid;
                b[ni][0] = f2tf32(Bs[cb][kk + tig][cn]);
                b[ni][1] = f2tf32(Bs[cb][kk + 4 + tig][cn]);
            }
#pragma unroll
            for (int mi = 0; mi < 2; mi++)
#pragma unroll
                for (int ni = 0; ni < 8; ni++)
                    mma_tf32(acc[mi][ni], a[mi], b[ni]);
        }
        __syncthreads();
        cb ^= 1;
    }

    // epilogue
    const float* __restrict__ bias = (z == 1) ? b2 : b3;

#pragma unroll
    for (int mi = 0; mi < 2; mi++) {
#pragma unroll
        for (int ni = 0; ni < 8; ni++) {
            const int col = bn + wn + ni * 8 + tig * 2;
            const int r0  = bm + wm + mi * 16 + gid;
            float v0 = acc[mi][ni][0], v1 = acc[mi][ni][1];
            float v2 = acc[mi][ni][2], v3 = acc[mi][ni][3];
            if (z >= 1) {
                const float bb0 = bias[col], bb1 = bias[col + 1];
                v0 += bb0; v1 += bb1; v2 += bb0; v3 += bb1;
            }
            if (z == 2) {
                v0 = sigmoidf_fast(v0); v1 = sigmoidf_fast(v1);
                v2 = sigmoidf_fast(v2); v3 = sigmoidf_fast(v3);
            }
            if (z == 0) {
                if (r0 < n)
                    *(__half2*)(g_support_h + (size_t)r0 * DF + col) = __floats2half2_rn(v0, v1);
                if (r0 + 8 < n)
                    *(__half2*)(g_support_h + (size_t)(r0 + 8) * DF + col) = __floats2half2_rn(v2, v3);
            } else {
                float* __restrict__ outp = (z == 1) ? g_trans : g_gate;
                if (r0 < n)
                    *(float2*)(outp + (size_t)r0 * DF + col) = make_float2(v0, v1);
                if (r0 + 8 < n)
                    *(float2*)(outp + (size_t)(r0 + 8) * DF + col) = make_float2(v2, v3);
            }
        }
    }
}

// ---------------- CSR build --------------------------------------------------
__global__ void zero_cnt_kernel(int n) {
    const int i = blockIdx.x * blockDim.x + threadIdx.x;
    if (i < n) g_row_cnt[i] = 0;
}

__global__ void hist_kernel(const int* __restrict__ er, int E) {
    for (int i = blockIdx.x * blockDim.x + threadIdx.x; i < E; i += gridDim.x * blockDim.x)
        atomicAdd(&g_row_cnt[er[i]], 1);
}

// phase A: per-block (512 elems) sums
__global__ __launch_bounds__(256) void scan_reduce_kernel(int n) {
    __shared__ int s[256];
    const int b = blockIdx.x, t = threadIdx.x;
    const int i0 = b * 512 + t;
    const int i1 = i0 + 256;
    int v = 0;
    if (i0 < n) v += g_row_cnt[i0];
    if (i1 < n) v += g_row_cnt[i1];
    s[t] = v;
    __syncthreads();
#pragma unroll
    for (int off = 128; off > 0; off >>= 1) {
        if (t < off) s[t] += s[t + off];
        __syncthreads();
    }
    if (t == 0) g_partials[b] = s[0];
}

// phase B: exclusive scan of block partials (nb <= 256), one block
__global__ __launch_bounds__(256) void scan_offsets_kernel(int nb) {
    __shared__ int s[256];
    const int t = threadIdx.x;
    const int v = (t < nb) ? g_partials[t] : 0;
    s[t] = v;
    __syncthreads();
#pragma unroll
    for (int off = 1; off < 256; off <<= 1) {
        const int u = (t >= off) ? s[t - off] : 0;
        __syncthreads();
        s[t] += u;
        __syncthreads();
    }
    if (t < nb) g_partials[t] = s[t] - v;   // exclusive
}

// phase C: per-block exclusive scan + global offset
__global__ __launch_bounds__(256) void scan_fill_kernel(int n) {
    __shared__ int s[256];
    const int b = blockIdx.x, t = threadIdx.x;
    const int i0 = b * 512 + 2 * t;
    const int c0 = (i0 < n)     ? g_row_cnt[i0]     : 0;
    const int c1 = (i0 + 1 < n) ? g_row_cnt[i0 + 1] : 0;
    s[t] = c0 + c1;
    __syncthreads();
#pragma unroll
    for (int off = 1; off < 256; off <<= 1) {
        const int u = (t >= off) ? s[t - off] : 0;
        __syncthreads();
        s[t] += u;
        __syncthreads();
    }
    const int excl = s[t] - (c0 + c1) + g_partials[b];
    if (i0 < n)     { g_row_start[i0]     = excl;      g_row_cur[i0]     = excl; }
    if (i0 + 1 < n) { g_row_start[i0 + 1] = excl + c0; g_row_cur[i0 + 1] = excl + c0; }
}

__global__ void scatter_kernel(const int* __restrict__ er, const int* __restrict__ ec,
                               const float* __restrict__ ev, int E) {
    for (int i = blockIdx.x * blockDim.x + threadIdx.x; i < E; i += gridDim.x * blockDim.x) {
        const int r = er[i];
        const int p = atomicAdd(&g_row_cur[r], 1);
        g_edges[p] = make_int2(ec[i], __float_as_int(ev[i]));
    }
}

// ---------------- aggregation + fused final epilogue -------------------------
// one block (64 threads) per output row; each thread owns 8 columns (16B fp16)
__device__ __forceinline__ void fma8_h(float acc[8], const uint4 raw, const float val) {
    const __half2 h0 = *reinterpret_cast<const __half2*>(&raw.x);
    const __half2 h1 = *reinterpret_cast<const __half2*>(&raw.y);
    const __half2 h2 = *reinterpret_cast<const __half2*>(&raw.z);
    const __half2 h3 = *reinterpret_cast<const __half2*>(&raw.w);
    const float2 f0 = __half22float2(h0);
    const float2 f1 = __half22float2(h1);
    const float2 f2 = __half22float2(h2);
    const float2 f3 = __half22float2(h3);
    acc[0] = fmaf(val, f0.x, acc[0]); acc[1] = fmaf(val, f0.y, acc[1]);
    acc[2] = fmaf(val, f1.x, acc[2]); acc[3] = fmaf(val, f1.y, acc[3]);
    acc[4] = fmaf(val, f2.x, acc[4]); acc[5] = fmaf(val, f2.y, acc[5]);
    acc[6] = fmaf(val, f3.x, acc[6]); acc[7] = fmaf(val, f3.y, acc[7]);
}

__global__ __launch_bounds__(64) void aggregate_kernel(
    const float* __restrict__ b1, float* __restrict__ out, int n)
{
    const int row = blockIdx.x;
    const int t   = threadIdx.x;
    const int c   = t << 3;

    const int start = g_row_start[row];
    const int deg   = g_row_cnt[row];

    float acc[8];
#pragma unroll
    for (int i = 0; i < 8; i++) acc[i] = 0.0f;

    __shared__ int2 se[64];

    for (int base = 0; base < deg; base += 64) {
        const int m = min(64, deg - base);
        if (t < m) se[t] = g_edges[start + base + t];
        __syncthreads();

        int i = 0;
        for (; i + 4 <= m; i += 4) {
            const int2 e0 = se[i], e1 = se[i + 1], e2 = se[i + 2], e3 = se[i + 3];
            const uint4 r0 = *reinterpret_cast<const uint4*>(g_support_h + (size_t)e0.x * DF + c);
            const uint4 r1 = *reinterpret_cast<const uint4*>(g_support_h + (size_t)e1.x * DF + c);
            const uint4 r2 = *reinterpret_cast<const uint4*>(g_support_h + (size_t)e2.x * DF + c);
            const uint4 r3 = *reinterpret_cast<const uint4*>(g_support_h + (size_t)e3.x * DF + c);
            fma8_h(acc, r0, __int_as_float(e0.y));
            fma8_h(acc, r1, __int_as_float(e1.y));
            fma8_h(acc, r2, __int_as_float(e2.y));
            fma8_h(acc, r3, __int_as_float(e3.y));
        }
        for (; i < m; i++) {
            const int2 e = se[i];
            const uint4 r = *reinterpret_cast<const uint4*>(g_support_h + (size_t)e.x * DF + c);
            fma8_h(acc, r, __int_as_float(e.y));
        }
        __syncthreads();
    }

    const size_t off = (size_t)row * DF + c;
    const float4 bb0 = *(const float4*)(b1 + c);
    const float4 bb1 = *(const float4*)(b1 + c + 4);
    const float4 tr0 = *(const float4*)(g_trans + off);
    const float4 tr1 = *(const float4*)(g_trans + off + 4);
    const float4 gt0 = *(const float4*)(g_gate + off);
    const float4 gt1 = *(const float4*)(g_gate + off + 4);

    float4 o0, o1;
    float r;
    r = fmaxf(acc[0] + bb0.x, 0.f);  o0.x = tr0.x + gt0.x * (r - tr0.x);
    r = fmaxf(acc[1] + bb0.y, 0.f);  o0.y = tr0.y + gt0.y * (r - tr0.y);
    r = fmaxf(acc[2] + bb0.z, 0.f);  o0.z = tr0.z + gt0.z * (r - tr0.z);
    r = fmaxf(acc[3] + bb0.w, 0.f);  o0.w = tr0.w + gt0.w * (r - tr0.w);
    r = fmaxf(acc[4] + bb1.x, 0.f);  o1.x = tr1.x + gt1.x * (r - tr1.x);
    r = fmaxf(acc[5] + bb1.y, 0.f);  o1.y = tr1.y + gt1.y * (r - tr1.y);
    r = fmaxf(acc[6] + bb1.z, 0.f);  o1.z = tr1.z + gt1.z * (r - tr1.z);
    r = fmaxf(acc[7] + bb1.w, 0.f);  o1.w = tr1.w + gt1.w * (r - tr1.w);
    *(float4*)(out + off)     = o0;
    *(float4*)(out + off + 4) = o1;
}

// ---------------- launch ------------------------------------------------------
extern "C" void kernel_launch(void* const* d_in, const int* in_sizes, int n_in,
                              void* d_out, int out_size)
{
    const float* x  = (const float*)d_in[0];
    const float* w1 = (const float*)d_in[1];
    const float* w2 = (const float*)d_in[2];
    const float* w3 = (const float*)d_in[3];
    const float* b1 = (const float*)d_in[4];
    const float* b2 = (const float*)d_in[5];
    const float* b3 = (const float*)d_in[6];
    const int*   er = (const int*)d_in[7];
    const int*   ec = (const int*)d_in[8];
    const float* ev = (const float*)d_in[9];

    const int n = in_sizes[0] / DF;   // 100000
    const int E = in_sizes[7];        // 3200000
    float* out = (float*)d_out;

    dim3 ggrid((n + 127) / 128, DF / 128, 3);
    gemm3_kernel<<<ggrid, 256>>>(x, w1, w2, w3, b2, b3, n);

    const int nb = (n + 511) / 512;   // <= 256
    zero_cnt_kernel<<<(n + 255) / 256, 256>>>(n);
    hist_kernel<<<2048, 256>>>(er, E);
    scan_reduce_kernel<<<nb, 256>>>(n);
    scan_offsets_kernel<<<1, 256>>>(nb);
    scan_fill_kernel<<<nb, 256>>>(n);
    scatter_kernel<<<2048, 256>>>(er, ec, ev, E);

    aggregate_kernel<<<n, 64>>>(b1, out, n);
}

// round 5
// speedup vs baseline: 1.7763x; 1.1356x over previous
#include <cuda_runtime.h>
#include <cuda_bf16.h>
#include <cuda_fp16.h>
#include <stdint.h>
#include <math.h>

#define DF 512
#define MAXN 100000
#define MAXE 3200000

// ---------------- device scratch (no dynamic allocation allowed) -------------
__device__ float  g_x32[(size_t)MAXN * DF];    // tf32-rounded x
__device__ float  g_w32[3 * DF * DF];          // tf32-rounded w1|w2|w3
__device__ __half g_support_h[(size_t)MAXN * DF];
__device__ float  g_trans[(size_t)MAXN * DF];
__device__ float  g_gate[(size_t)MAXN * DF];
__device__ int    g_row_cnt[MAXN];
__device__ int    g_row_start[MAXN];
__device__ int    g_row_cur[MAXN];
__device__ int    g_partials[256];
__device__ int2   g_edges[MAXE];   // (col, val-as-bits) grouped by row

// ---------------- helpers ----------------------------------------------------
__device__ __forceinline__ unsigned f2tf32(float f) {
    unsigned r;
    asm("cvt.rna.tf32.f32 %0, %1;" : "=r"(r) : "f"(f));
    return r;
}

__device__ __forceinline__ void mma_tf32(float c[4], const unsigned a[4], const unsigned b[2]) {
    asm volatile(
        "mma.sync.aligned.m16n8k8.row.col.f32.tf32.tf32.f32 "
        "{%0,%1,%2,%3}, {%4,%5,%6,%7}, {%8,%9}, {%0,%1,%2,%3};"
        : "+f"(c[0]), "+f"(c[1]), "+f"(c[2]), "+f"(c[3])
        : "r"(a[0]), "r"(a[1]), "r"(a[2]), "r"(a[3]), "r"(b[0]), "r"(b[1]));
}

__device__ __forceinline__ void cp16(unsigned int dst, const void* src, bool valid) {
    int sz = valid ? 16 : 0;
    asm volatile("cp.async.cg.shared.global [%0], [%1], 16, %2;"
                 :: "r"(dst), "l"(src), "r"(sz));
}
__device__ __forceinline__ void cp_commit() { asm volatile("cp.async.commit_group;"); }
__device__ __forceinline__ void cp_wait1()  { asm volatile("cp.async.wait_group 1;"); }

__device__ __forceinline__ float sigmoidf_fast(float v) {
    return 1.0f / (1.0f + __expf(-v));
}

// ---------------- tf32 pre-rounding passes ------------------------------------
__global__ __launch_bounds__(256) void cvt_x_kernel(const float* __restrict__ x, int total4) {
    for (int i = blockIdx.x * blockDim.x + threadIdx.x; i < total4; i += gridDim.x * blockDim.x) {
        float4 v = reinterpret_cast<const float4*>(x)[i];
        v.x = __uint_as_float(f2tf32(v.x));
        v.y = __uint_as_float(f2tf32(v.y));
        v.z = __uint_as_float(f2tf32(v.z));
        v.w = __uint_as_float(f2tf32(v.w));
        reinterpret_cast<float4*>(g_x32)[i] = v;
    }
}

__global__ __launch_bounds__(256) void cvt_w_kernel(
    const float* __restrict__ w1, const float* __restrict__ w2, const float* __restrict__ w3) {
    const int per = DF * DF / 4;   // 65536 float4 per matrix
    const int i = blockIdx.x * blockDim.x + threadIdx.x;   // 0 .. 3*per-1
    if (i >= 3 * per) return;
    const int which = i / per;
    const int j = i - which * per;
    const float* src = (which == 0) ? w1 : ((which == 1) ? w2 : w3);
    float4 v = reinterpret_cast<const float4*>(src)[j];
    v.x = __uint_as_float(f2tf32(v.x));
    v.y = __uint_as_float(f2tf32(v.y));
    v.z = __uint_as_float(f2tf32(v.z));
    v.w = __uint_as_float(f2tf32(v.w));
    reinterpret_cast<float4*>(g_w32)[i] = v;
}

// ---------------- fused triple GEMM (tf32 tensor cores, cp.async pipeline) ---
// Block tile 128(M) x 128(N), K-tile 32, double-buffered (dynamic smem).
// grid.x = 12 combos (4 bn x 3 z) so consecutive CTAs share the A tile in L2;
// grid.y = bm. Inputs are pre-rounded to tf32, so inner loop is LDS+MMA only.
#define AS_STRIDE 36
#define BS_STRIDE 136
#define A_BUF (128 * AS_STRIDE)   // 4608 floats
#define B_BUF (32 * BS_STRIDE)    // 4352 floats
#define GEMM_SMEM ((2 * A_BUF + 2 * B_BUF) * 4)   // 71680 bytes

__global__ __launch_bounds__(256) void gemm3_kernel(
    const float* __restrict__ b2, const float* __restrict__ b3, int n)
{
    extern __shared__ float sm[];
    float* As = sm;                 // [2][128][36]
    float* Bs = sm + 2 * A_BUF;     // [2][32][136]

    const int combo = blockIdx.x;       // 0..11
    const int bn = (combo & 3) * 128;
    const int z  = combo >> 2;          // 0..2
    const int bm = blockIdx.y * 128;
    const float* __restrict__ wz = g_w32 + (size_t)z * DF * DF;

    const int t    = threadIdx.x;
    const int lane = t & 31;
    const int warp = t >> 5;
    const int wm   = (warp & 3) * 32;
    const int wn   = (warp >> 2) * 64;
    const int gid  = lane >> 2;
    const int tig  = lane & 3;

    float acc[2][8][4];
#pragma unroll
    for (int mi = 0; mi < 2; mi++)
#pragma unroll
        for (int ni = 0; ni < 8; ni++)
#pragma unroll
            for (int r = 0; r < 4; r++) acc[mi][ni][r] = 0.0f;

    const int NT = DF / 32;   // 16 k-tiles

    // ---- prefetch helper (inlined loop) ----
    // A: 128x32 = 1024 float4, 4/thread. B: 32x128 = 1024 float4, 4/thread.
#define DO_PREFETCH(BF, K0)                                                          \
    {                                                                                \
        _Pragma("unroll")                                                            \
        for (int i = 0; i < 4; i++) {                                                \
            const int idx = t + i * 256;                                             \
            const int r_  = idx >> 3;                                                \
            const int c_  = (idx & 7) * 4;                                           \
            unsigned int d_ = (unsigned int)__cvta_generic_to_shared(                \
                &As[(BF) * A_BUF + r_ * AS_STRIDE + c_]);                            \
            cp16(d_, g_x32 + (size_t)(bm + r_) * DF + (K0) + c_, (bm + r_) < n);     \
        }                                                                            \
        _Pragma("unroll")                                                            \
        for (int i = 0; i < 4; i++) {                                                \
            const int idx = t + i * 256;                                             \
            const int r_  = idx >> 5;                                                \
            const int c_  = (idx & 31) * 4;                                          \
            unsigned int d_ = (unsigned int)__cvta_generic_to_shared(                \
                &Bs[(BF) * B_BUF + r_ * BS_STRIDE + c_]);                            \
            cp16(d_, wz + (size_t)((K0) + r_) * DF + bn + c_, true);                 \
        }                                                                            \
    }

    int cb = 0;
    DO_PREFETCH(0, 0)
    cp_commit();

    for (int kt = 0; kt < NT; kt++) {
        if (kt + 1 < NT) DO_PREFETCH(cb ^ 1, (kt + 1) * 32)
        cp_commit();
        cp_wait1();
        __syncthreads();

        const float* Ab = As + cb * A_BUF;
        const float* Bb = Bs + cb * B_BUF;

#pragma unroll
        for (int kk = 0; kk < 32; kk += 8) {
            unsigned a[2][4];
#pragma unroll
            for (int mi = 0; mi < 2; mi++) {
                const int r = wm + mi * 16 + gid;
                a[mi][0] = __float_as_uint(Ab[r * AS_STRIDE + kk + tig]);
                a[mi][1] = __float_as_uint(Ab[(r + 8) * AS_STRIDE + kk + tig]);
                a[mi][2] = __float_as_uint(Ab[r * AS_STRIDE + kk + 4 + tig]);
                a[mi][3] = __float_as_uint(Ab[(r + 8) * AS_STRIDE + kk + 4 + tig]);
            }
            unsigned b[8][2];
#pragma unroll
            for (int ni = 0; ni < 8; ni++) {
                const int cn = wn + ni * 8 + gid;
                b[ni][0] = __float_as_uint(Bb[(kk + tig) * BS_STRIDE + cn]);
                b[ni][1] = __float_as_uint(Bb[(kk + 4 + tig) * BS_STRIDE + cn]);
            }
#pragma unroll
            for (int mi = 0; mi < 2; mi++)
#pragma unroll
                for (int ni = 0; ni < 8; ni++)
                    mma_tf32(acc[mi][ni], a[mi], b[ni]);
        }
        __syncthreads();
        cb ^= 1;
    }
#undef DO_PREFETCH

    // epilogue
    const float* __restrict__ bias = (z == 1) ? b2 : b3;

#pragma unroll
    for (int mi = 0; mi < 2; mi++) {
#pragma unroll
        for (int ni = 0; ni < 8; ni++) {
            const int col = bn + wn + ni * 8 + tig * 2;
            const int r0  = bm + wm + mi * 16 + gid;
            float v0 = acc[mi][ni][0], v1 = acc[mi][ni][1];
            float v2 = acc[mi][ni][2], v3 = acc[mi][ni][3];
            if (z >= 1) {
                const float bb0 = bias[col], bb1 = bias[col + 1];
                v0 += bb0; v1 += bb1; v2 += bb0; v3 += bb1;
            }
            if (z == 2) {
                v0 = sigmoidf_fast(v0); v1 = sigmoidf_fast(v1);
                v2 = sigmoidf_fast(v2); v3 = sigmoidf_fast(v3);
            }
            if (z == 0) {
                if (r0 < n)
                    *(__half2*)(g_support_h + (size_t)r0 * DF + col) = __floats2half2_rn(v0, v1);
                if (r0 + 8 < n)
                    *(__half2*)(g_support_h + (size_t)(r0 + 8) * DF + col) = __floats2half2_rn(v2, v3);
            } else {
                float* __restrict__ outp = (z == 1) ? g_trans : g_gate;
                if (r0 < n)
                    *(float2*)(outp + (size_t)r0 * DF + col) = make_float2(v0, v1);
                if (r0 + 8 < n)
                    *(float2*)(outp + (size_t)(r0 + 8) * DF + col) = make_float2(v2, v3);
            }
        }
    }
}

// ---------------- CSR build --------------------------------------------------
__global__ void zero_cnt_kernel(int n) {
    const int i = blockIdx.x * blockDim.x + threadIdx.x;
    if (i < n) g_row_cnt[i] = 0;
}

__global__ void hist_kernel(const int* __restrict__ er, int E) {
    for (int i = blockIdx.x * blockDim.x + threadIdx.x; i < E; i += gridDim.x * blockDim.x)
        atomicAdd(&g_row_cnt[er[i]], 1);
}

__global__ __launch_bounds__(256) void scan_reduce_kernel(int n) {
    __shared__ int s[256];
    const int b = blockIdx.x, t = threadIdx.x;
    const int i0 = b * 512 + t;
    const int i1 = i0 + 256;
    int v = 0;
    if (i0 < n) v += g_row_cnt[i0];
    if (i1 < n) v += g_row_cnt[i1];
    s[t] = v;
    __syncthreads();
#pragma unroll
    for (int off = 128; off > 0; off >>= 1) {
        if (t < off) s[t] += s[t + off];
        __syncthreads();
    }
    if (t == 0) g_partials[b] = s[0];
}

__global__ __launch_bounds__(256) void scan_offsets_kernel(int nb) {
    __shared__ int s[256];
    const int t = threadIdx.x;
    const int v = (t < nb) ? g_partials[t] : 0;
    s[t] = v;
    __syncthreads();
#pragma unroll
    for (int off = 1; off < 256; off <<= 1) {
        const int u = (t >= off) ? s[t - off] : 0;
        __syncthreads();
        s[t] += u;
        __syncthreads();
    }
    if (t < nb) g_partials[t] = s[t] - v;   // exclusive
}

__global__ __launch_bounds__(256) void scan_fill_kernel(int n) {
    __shared__ int s[256];
    const int b = blockIdx.x, t = threadIdx.x;
    const int i0 = b * 512 + 2 * t;
    const int c0 = (i0 < n)     ? g_row_cnt[i0]     : 0;
    const int c1 = (i0 + 1 < n) ? g_row_cnt[i0 + 1] : 0;
    s[t] = c0 + c1;
    __syncthreads();
#pragma unroll
    for (int off = 1; off < 256; off <<= 1) {
        const int u = (t >= off) ? s[t - off] : 0;
        __syncthreads();
        s[t] += u;
        __syncthreads();
    }
    const int excl = s[t] - (c0 + c1) + g_partials[b];
    if (i0 < n)     { g_row_start[i0]     = excl;      g_row_cur[i0]     = excl; }
    if (i0 + 1 < n) { g_row_start[i0 + 1] = excl + c0; g_row_cur[i0 + 1] = excl + c0; }
}

__global__ void scatter_kernel(const int* __restrict__ er, const int* __restrict__ ec,
                               const float* __restrict__ ev, int E) {
    for (int i = blockIdx.x * blockDim.x + threadIdx.x; i < E; i += gridDim.x * blockDim.x) {
        const int r = er[i];
        const int p = atomicAdd(&g_row_cur[r], 1);
        g_edges[p] = make_int2(ec[i], __float_as_int(ev[i]));
    }
}

// ---------------- aggregation + fused final epilogue -------------------------
__device__ __forceinline__ void fma8_h(float acc[8], const uint4 raw, const float val) {
    const __half2 h0 = *reinterpret_cast<const __half2*>(&raw.x);
    const __half2 h1 = *reinterpret_cast<const __half2*>(&raw.y);
    const __half2 h2 = *reinterpret_cast<const __half2*>(&raw.z);
    const __half2 h3 = *reinterpret_cast<const __half2*>(&raw.w);
    const float2 f0 = __half22float2(h0);
    const float2 f1 = __half22float2(h1);
    const float2 f2 = __half22float2(h2);
    const float2 f3 = __half22float2(h3);
    acc[0] = fmaf(val, f0.x, acc[0]); acc[1] = fmaf(val, f0.y, acc[1]);
    acc[2] = fmaf(val, f1.x, acc[2]); acc[3] = fmaf(val, f1.y, acc[3]);
    acc[4] = fmaf(val, f2.x, acc[4]); acc[5] = fmaf(val, f2.y, acc[5]);
    acc[6] = fmaf(val, f3.x, acc[6]); acc[7] = fmaf(val, f3.y, acc[7]);
}

__global__ __launch_bounds__(64) void aggregate_kernel(
    const float* __restrict__ b1, float* __restrict__ out, int n)
{
    const int row = blockIdx.x;
    const int t   = threadIdx.x;
    const int c   = t << 3;

    const int start = g_row_start[row];
    const int deg   = g_row_cnt[row];

    float acc[8];
#pragma unroll
    for (int i = 0; i < 8; i++) acc[i] = 0.0f;

    __shared__ int2 se[64];

    for (int base = 0; base < deg; base += 64) {
        const int m = min(64, deg - base);
        if (t < m) se[t] = g_edges[start + base + t];
        __syncthreads();

        int i = 0;
        for (; i + 4 <= m; i += 4) {
            const int2 e0 = se[i], e1 = se[i + 1], e2 = se[i + 2], e3 = se[i + 3];
            const uint4 r0 = *reinterpret_cast<const uint4*>(g_support_h + (size_t)e0.x * DF + c);
            const uint4 r1 = *reinterpret_cast<const uint4*>(g_support_h + (size_t)e1.x * DF + c);
            const uint4 r2 = *reinterpret_cast<const uint4*>(g_support_h + (size_t)e2.x * DF + c);
            const uint4 r3 = *reinterpret_cast<const uint4*>(g_support_h + (size_t)e3.x * DF + c);
            fma8_h(acc, r0, __int_as_float(e0.y));
            fma8_h(acc, r1, __int_as_float(e1.y));
            fma8_h(acc, r2, __int_as_float(e2.y));
            fma8_h(acc, r3, __int_as_float(e3.y));
        }
        for (; i < m; i++) {
            const int2 e = se[i];
            const uint4 r = *reinterpret_cast<const uint4*>(g_support_h + (size_t)e.x * DF + c);
            fma8_h(acc, r, __int_as_float(e.y));
        }
        __syncthreads();
    }

    const size_t off = (size_t)row * DF + c;
    const float4 bb0 = *(const float4*)(b1 + c);
    const float4 bb1 = *(const float4*)(b1 + c + 4);
    const float4 tr0 = *(const float4*)(g_trans + off);
    const float4 tr1 = *(const float4*)(g_trans + off + 4);
    const float4 gt0 = *(const float4*)(g_gate + off);
    const float4 gt1 = *(const float4*)(g_gate + off + 4);

    float4 o0, o1;
    float r;
    r = fmaxf(acc[0] + bb0.x, 0.f);  o0.x = tr0.x + gt0.x * (r - tr0.x);
    r = fmaxf(acc[1] + bb0.y, 0.f);  o0.y = tr0.y + gt0.y * (r - tr0.y);
    r = fmaxf(acc[2] + bb0.z, 0.f);  o0.z = tr0.z + gt0.z * (r - tr0.z);
    r = fmaxf(acc[3] + bb0.w, 0.f);  o0.w = tr0.w + gt0.w * (r - tr0.w);
    r = fmaxf(acc[4] + bb1.x, 0.f);  o1.x = tr1.x + gt1.x * (r - tr1.x);
    r = fmaxf(acc[5] + bb1.y, 0.f);  o1.y = tr1.y + gt1.y * (r - tr1.y);
    r = fmaxf(acc[6] + bb1.z, 0.f);  o1.z = tr1.z + gt1.z * (r - tr1.z);
    r = fmaxf(acc[7] + bb1.w, 0.f);  o1.w = tr1.w + gt1.w * (r - tr1.w);
    *(float4*)(out + off)     = o0;
    *(float4*)(out + off + 4) = o1;
}

// ---------------- launch ------------------------------------------------------
extern "C" void kernel_launch(void* const* d_in, const int* in_sizes, int n_in,
                              void* d_out, int out_size)
{
    const float* x  = (const float*)d_in[0];
    const float* w1 = (const float*)d_in[1];
    const float* w2 = (const float*)d_in[2];
    const float* w3 = (const float*)d_in[3];
    const float* b1 = (const float*)d_in[4];
    const float* b2 = (const float*)d_in[5];
    const float* b3 = (const float*)d_in[6];
    const int*   er = (const int*)d_in[7];
    const int*   ec = (const int*)d_in[8];
    const float* ev = (const float*)d_in[9];

    const int n = in_sizes[0] / DF;   // 100000
    const int E = in_sizes[7];        // 3200000
    float* out = (float*)d_out;

    static bool attr_set = false;
    if (!attr_set) {
        cudaFuncSetAttribute(gemm3_kernel, cudaFuncAttributeMaxDynamicSharedMemorySize, GEMM_SMEM);
        attr_set = true;
    }

    // tf32 pre-rounding
    const int total4 = n * DF / 4;
    cvt_x_kernel<<<2048, 256>>>(x, total4);
    cvt_w_kernel<<<(3 * DF * DF / 4 + 255) / 256, 256>>>(w1, w2, w3);

    dim3 ggrid(12, (n + 127) / 128, 1);
    gemm3_kernel<<<ggrid, 256, GEMM_SMEM>>>(b2, b3, n);

    const int nb = (n + 511) / 512;   // <= 256
    zero_cnt_kernel<<<(n + 255) / 256, 256>>>(n);
    hist_kernel<<<2048, 256>>>(er, E);
    scan_reduce_kernel<<<nb, 256>>>(n);
    scan_offsets_kernel<<<1, 256>>>(nb);
    scan_fill_kernel<<<nb, 256>>>(n);
    scatter_kernel<<<2048, 256>>>(er, ec, ev, E);

    aggregate_kernel<<<n, 64>>>(b1, out, n);
}